// round 1
// baseline (speedup 1.0000x reference)
#include <cuda_runtime.h>
#include <math.h>

// Problem constants
#define BB 2
#define SS 2048
#define DD 2048
#define HH 16
#define HD_ 128
#define ND_ 64
#define RD_ 64
#define RR 512
#define MM (BB*SS)   // 4096

// Scratch (device globals: no allocation allowed)
__device__ float g_q   [(size_t)MM*DD];       // roped q, [b*S+s, h*128+d]
__device__ float g_ckv [(size_t)MM*RR];
__device__ float g_kn  [(size_t)MM*HH*ND_];   // k_nope [b*S+s, h*64+d]
__device__ float g_kr  [(size_t)MM*RD_];      // roped k_rope
__device__ float g_v   [(size_t)MM*DD];
__device__ float g_attn[(size_t)MM*DD];

// ---------------------------------------------------------------------------
// C[M,N] = A[M,K] @ W[N,K]^T   (128x128 tile, BK=16, 256 thr, 8x8/thread)
// M multiple of 128, K multiple of 16; N guarded.
// ---------------------------------------------------------------------------
__global__ void __launch_bounds__(256) gemm_nt(const float* __restrict__ A,
                                               const float* __restrict__ W,
                                               float* __restrict__ C,
                                               int M, int N, int K) {
    __shared__ float As[16][128];
    __shared__ float Bs[16][128];
    int tid = threadIdx.x;
    int tx = tid & 15, ty = tid >> 4;
    int row0 = blockIdx.y * 128;
    int col0 = blockIdx.x * 128;
    float acc[8][8];
#pragma unroll
    for (int i = 0; i < 8; i++)
#pragma unroll
        for (int j = 0; j < 8; j++) acc[i][j] = 0.f;

    for (int k0 = 0; k0 < K; k0 += 16) {
#pragma unroll
        for (int t = 0; t < 2; t++) {
            int idx = tid + t * 256;      // 0..511 float4 slots
            int r = idx >> 2;             // 0..127
            int c = (idx & 3) << 2;       // 0,4,8,12
            float4 va = *(const float4*)(A + (size_t)(row0 + r) * K + k0 + c);
            As[c][r] = va.x; As[c+1][r] = va.y; As[c+2][r] = va.z; As[c+3][r] = va.w;
            int gc = col0 + r;
            float4 vb = make_float4(0.f, 0.f, 0.f, 0.f);
            if (gc < N) vb = *(const float4*)(W + (size_t)gc * K + k0 + c);
            Bs[c][r] = vb.x; Bs[c+1][r] = vb.y; Bs[c+2][r] = vb.z; Bs[c+3][r] = vb.w;
        }
        __syncthreads();
#pragma unroll
        for (int kk = 0; kk < 16; kk++) {
            float a[8], b[8];
            *(float4*)(a)     = *(float4*)&As[kk][ty * 8];
            *(float4*)(a + 4) = *(float4*)&As[kk][ty * 8 + 4];
            *(float4*)(b)     = *(float4*)&Bs[kk][tx * 8];
            *(float4*)(b + 4) = *(float4*)&Bs[kk][tx * 8 + 4];
#pragma unroll
            for (int i = 0; i < 8; i++)
#pragma unroll
                for (int j = 0; j < 8; j++)
                    acc[i][j] += a[i] * b[j];
        }
        __syncthreads();
    }
#pragma unroll
    for (int i = 0; i < 8; i++) {
        int r = row0 + ty * 8 + i;
#pragma unroll
        for (int j = 0; j < 8; j++) {
            int c = col0 + tx * 8 + j;
            if (c < N) C[(size_t)r * N + c] = acc[i][j];
        }
    }
}

// ---------------------------------------------------------------------------
// RoPE (interleaved pairs): out[2i] = x0*cos - x1*sin; out[2i+1] = x1*cos + x0*sin
// freq_i = 10000^(-i/32), i = 0..31, angle = s * freq_i
// ---------------------------------------------------------------------------
__global__ void rope_q_kernel(float* __restrict__ q) {
    int idx = blockIdx.x * blockDim.x + threadIdx.x;
    if (idx >= MM * HH * 32) return;
    int i  = idx & 31;
    int h  = (idx >> 5) & (HH - 1);
    int ms = idx >> 9;               // b*S+s
    int s  = ms & (SS - 1);
    float f = exp2f(-(float)i * (1.f / 32.f) * log2f(10000.f));
    float ang = (float)s * f;
    float sn, c;
    sincosf(ang, &sn, &c);
    float* base = q + (size_t)ms * DD + h * HD_ + ND_ + 2 * i;
    float x0 = base[0], x1 = base[1];
    base[0] = x0 * c - x1 * sn;
    base[1] = x1 * c + x0 * sn;
}

__global__ void rope_k_kernel(float* __restrict__ kr) {
    int idx = blockIdx.x * blockDim.x + threadIdx.x;
    if (idx >= MM * 32) return;
    int i  = idx & 31;
    int ms = idx >> 5;
    int s  = ms & (SS - 1);
    float f = exp2f(-(float)i * (1.f / 32.f) * log2f(10000.f));
    float ang = (float)s * f;
    float sn, c;
    sincosf(ang, &sn, &c);
    float* base = kr + (size_t)ms * RD_ + 2 * i;
    float x0 = base[0], x1 = base[1];
    base[0] = x0 * c - x1 * sn;
    base[1] = x1 * c + x0 * sn;
}

// ---------------------------------------------------------------------------
// Flash attention, causal. 64 q-rows x 64 k-rows tiles, 128-d q/k (nope+rope),
// 128-d v. 256 threads = 16x16; each thread: 4x4 of S, 4x8 of O.
// Smem: Qs[64][128] | KsT[128][64] | Vs[64][128] | Ps[64][64] = 114688 B
// ---------------------------------------------------------------------------
#define ATTN_SMEM ((64*128 + 128*64 + 64*128 + 64*64) * 4)

__global__ void __launch_bounds__(256) mla_attn_kernel(
        const float* __restrict__ q,  const float* __restrict__ knope,
        const float* __restrict__ kr, const float* __restrict__ v,
        float* __restrict__ out) {
    extern __shared__ float sm[];
    float* Qs  = sm;                 // [64][128]
    float* KsT = Qs  + 64 * 128;     // [128][64]  (dim-major)
    float* Vs  = KsT + 128 * 64;     // [64][128]
    float* Ps  = Vs  + 64 * 128;     // [64][64]

    int qb = blockIdx.x, h = blockIdx.y, b = blockIdx.z;
    int tid = threadIdx.x;
    int tx = tid & 15, ty = tid >> 4;
    int q0 = qb * 64;
    size_t bs = (size_t)b * SS;

    // Load Q tile (rope part already applied in-place)
#pragma unroll
    for (int t = 0; t < 8; t++) {
        int idx = tid + t * 256;     // 2048 float4
        int r = idx >> 5;
        int c = (idx & 31) << 2;
        *(float4*)&Qs[r * 128 + c] =
            *(const float4*)(q + (bs + q0 + r) * DD + h * HD_ + c);
    }

    float m_[4], l_[4], O[4][8];
#pragma unroll
    for (int i = 0; i < 4; i++) {
        m_[i] = -1e30f; l_[i] = 0.f;
#pragma unroll
        for (int d = 0; d < 8; d++) O[i][d] = 0.f;
    }
    const float scale = 0.08838834764831845f;  // 1/sqrt(128)
    __syncthreads();

    for (int kb = 0; kb <= qb; kb++) {
        int k0 = kb * 64;
        // Load K transposed (nope 0..63, rope 64..127) and V
#pragma unroll
        for (int t = 0; t < 4; t++) {
            int idx = tid + t * 256;     // 1024 float4 per half
            int r = idx >> 4;            // 0..63
            int c = (idx & 15) << 2;     // 0..60
            float4 kn = *(const float4*)(knope + (bs + k0 + r) * (HH * ND_) + h * ND_ + c);
            KsT[(c    ) * 64 + r] = kn.x;
            KsT[(c + 1) * 64 + r] = kn.y;
            KsT[(c + 2) * 64 + r] = kn.z;
            KsT[(c + 3) * 64 + r] = kn.w;
            float4 kp = *(const float4*)(kr + (bs + k0 + r) * RD_ + c);
            KsT[(64 + c    ) * 64 + r] = kp.x;
            KsT[(64 + c + 1) * 64 + r] = kp.y;
            KsT[(64 + c + 2) * 64 + r] = kp.z;
            KsT[(64 + c + 3) * 64 + r] = kp.w;
        }
#pragma unroll
        for (int t = 0; t < 8; t++) {
            int idx = tid + t * 256;
            int r = idx >> 5;
            int c = (idx & 31) << 2;
            *(float4*)&Vs[r * 128 + c] =
                *(const float4*)(v + (bs + k0 + r) * DD + h * HD_ + c);
        }
        __syncthreads();

        // S = Q @ K^T  (4x4 per thread)
        float sacc[4][4];
#pragma unroll
        for (int i = 0; i < 4; i++)
#pragma unroll
            for (int j = 0; j < 4; j++) sacc[i][j] = 0.f;

#pragma unroll 8
        for (int kk = 0; kk < 128; kk++) {
            float4 kv = *(float4*)&KsT[kk * 64 + tx * 4];
            float kvr[4] = {kv.x, kv.y, kv.z, kv.w};
#pragma unroll
            for (int i = 0; i < 4; i++) {
                float qv = Qs[(ty * 4 + i) * 128 + kk];
#pragma unroll
                for (int j = 0; j < 4; j++)
                    sacc[i][j] += qv * kvr[j];
            }
        }

        // Online softmax per row (row groups of 16 lanes share same ty)
#pragma unroll
        for (int i = 0; i < 4; i++) {
            int qi = q0 + ty * 4 + i;
#pragma unroll
            for (int j = 0; j < 4; j++) {
                int ki = k0 + tx * 4 + j;
                sacc[i][j] = (ki <= qi) ? sacc[i][j] * scale : -1e30f;
            }
            float mloc = fmaxf(fmaxf(sacc[i][0], sacc[i][1]),
                               fmaxf(sacc[i][2], sacc[i][3]));
#pragma unroll
            for (int off = 8; off >= 1; off >>= 1)
                mloc = fmaxf(mloc, __shfl_xor_sync(0xffffffffu, mloc, off, 16));
            float mnew = fmaxf(m_[i], mloc);
            float corr = __expf(m_[i] - mnew);
            float rs = 0.f;
#pragma unroll
            for (int j = 0; j < 4; j++) {
                float p = __expf(sacc[i][j] - mnew);
                Ps[(ty * 4 + i) * 64 + tx * 4 + j] = p;
                rs += p;
            }
#pragma unroll
            for (int off = 8; off >= 1; off >>= 1)
                rs += __shfl_xor_sync(0xffffffffu, rs, off, 16);
            l_[i] = l_[i] * corr + rs;
            m_[i] = mnew;
#pragma unroll
            for (int d = 0; d < 8; d++) O[i][d] *= corr;
        }
        __syncthreads();

        // O += P @ V
#pragma unroll 4
        for (int k = 0; k < 64; k++) {
            float4 v0 = *(float4*)&Vs[k * 128 + tx * 8];
            float4 v1 = *(float4*)&Vs[k * 128 + tx * 8 + 4];
            float vv[8] = {v0.x, v0.y, v0.z, v0.w, v1.x, v1.y, v1.z, v1.w};
#pragma unroll
            for (int i = 0; i < 4; i++) {
                float p = Ps[(ty * 4 + i) * 64 + k];
#pragma unroll
                for (int d = 0; d < 8; d++)
                    O[i][d] += p * vv[d];
            }
        }
        __syncthreads();  // protect smem before next tile's loads
    }

    // Write normalized output: [b,s, h*128 + d]
#pragma unroll
    for (int i = 0; i < 4; i++) {
        float inv = 1.f / l_[i];
        size_t rowp = (bs + q0 + ty * 4 + i) * DD + h * HD_ + tx * 8;
#pragma unroll
        for (int d = 0; d < 8; d++)
            out[rowp + d] = O[i][d] * inv;
    }
}

// ---------------------------------------------------------------------------
extern "C" void kernel_launch(void* const* d_in, const int* in_sizes, int n_in,
                              void* d_out, int out_size) {
    const float* x   = (const float*)d_in[0];
    const float* wq  = (const float*)d_in[1];
    const float* wkd = (const float*)d_in[2];
    const float* wku = (const float*)d_in[3];
    const float* wkr = (const float*)d_in[4];
    const float* wvu = (const float*)d_in[5];
    const float* wo  = (const float*)d_in[6];
    float* out = (float*)d_out;

    float *pq, *pckv, *pkn, *pkr, *pv, *pattn;
    cudaGetSymbolAddress((void**)&pq,    g_q);
    cudaGetSymbolAddress((void**)&pckv,  g_ckv);
    cudaGetSymbolAddress((void**)&pkn,   g_kn);
    cudaGetSymbolAddress((void**)&pkr,   g_kr);
    cudaGetSymbolAddress((void**)&pv,    g_v);
    cudaGetSymbolAddress((void**)&pattn, g_attn);

    cudaFuncSetAttribute(mla_attn_kernel,
                         cudaFuncAttributeMaxDynamicSharedMemorySize, ATTN_SMEM);

    // q = x @ wq^T
    gemm_nt<<<dim3(DD / 128, MM / 128), 256>>>(x, wq, pq, MM, DD, DD);
    // c_kv = x @ w_kv_down^T
    gemm_nt<<<dim3(RR / 128, MM / 128), 256>>>(x, wkd, pckv, MM, RR, DD);
    // k_rope_pre = x @ w_k_rope^T   (N=64 < tile, guarded)
    gemm_nt<<<dim3(1, MM / 128), 256>>>(x, wkr, pkr, MM, RD_, DD);
    // k_nope = c_kv @ w_k_up^T
    gemm_nt<<<dim3((HH * ND_) / 128, MM / 128), 256>>>(pckv, wku, pkn, MM, HH * ND_, RR);
    // v = c_kv @ w_v_up^T
    gemm_nt<<<dim3(DD / 128, MM / 128), 256>>>(pckv, wvu, pv, MM, DD, RR);
    // RoPE in place
    rope_q_kernel<<<(MM * HH * 32) / 256, 256>>>(pq);
    rope_k_kernel<<<(MM * 32) / 256, 256>>>(pkr);
    // Flash attention
    mla_attn_kernel<<<dim3(SS / 64, HH, BB), 256, ATTN_SMEM>>>(pq, pkn, pkr, pv, pattn);
    // final = attn_out @ wo^T
    gemm_nt<<<dim3(DD / 128, MM / 128), 256>>>(pattn, wo, out, MM, DD, DD);
}

// round 2
// speedup vs baseline: 1.8064x; 1.8064x over previous
#include <cuda_runtime.h>
#include <math.h>

// Problem constants
#define BB 2
#define SS 2048
#define DD 2048
#define HH 16
#define HD_ 128
#define ND_ 64
#define RD_ 64
#define RR 512
#define MM (BB*SS)   // 4096

// Scratch (device globals: no allocation allowed)
__device__ float g_q   [(size_t)MM*DD];
__device__ float g_ckv [(size_t)MM*RR];
__device__ float g_kn  [(size_t)MM*HH*ND_];
__device__ float g_kr  [(size_t)MM*RD_];
__device__ float g_v   [(size_t)MM*DD];
__device__ float g_attn[(size_t)MM*DD];

__device__ __forceinline__ unsigned f2tf(float x) {
    unsigned y;
    asm("cvt.rna.tf32.f32 %0, %1;" : "=r"(y) : "f"(x));
    return y;
}

__device__ __forceinline__ void mma_tf32(float d[4], const unsigned a[4],
                                         const unsigned b[2]) {
    asm volatile(
        "mma.sync.aligned.m16n8k8.row.col.f32.tf32.tf32.f32 "
        "{%0,%1,%2,%3}, {%4,%5,%6,%7}, {%8,%9}, {%0,%1,%2,%3};\n"
        : "+f"(d[0]), "+f"(d[1]), "+f"(d[2]), "+f"(d[3])
        : "r"(a[0]), "r"(a[1]), "r"(a[2]), "r"(a[3]),
          "r"(b[0]), "r"(b[1]));
}

// ---------------------------------------------------------------------------
// C[M,N] = A[M,K] @ W[N,K]^T  via tf32 tensor cores.
// Block 128x128, BK=32, 256 threads = 8 warps (2m x 4n), warp tile 64x32.
// ---------------------------------------------------------------------------
__global__ void __launch_bounds__(256) gemm_tf32(const float* __restrict__ A,
                                                 const float* __restrict__ W,
                                                 float* __restrict__ C,
                                                 int M, int N, int K) {
    __shared__ unsigned As[128][36];   // [m][k] pad 4 -> conflict-free frags
    __shared__ unsigned Bs[128][36];   // [n][k]
    int tid = threadIdx.x;
    int lane = tid & 31, warp = tid >> 5;
    int wm = (warp & 1) * 64;
    int wn = (warp >> 1) * 32;
    int row0 = blockIdx.y * 128, col0 = blockIdx.x * 128;

    float acc[4][4][4];
#pragma unroll
    for (int i = 0; i < 4; i++)
#pragma unroll
        for (int j = 0; j < 4; j++)
#pragma unroll
            for (int r = 0; r < 4; r++) acc[i][j][r] = 0.f;

    int lr = tid >> 3;          // 0..31
    int lc = (tid & 7) * 4;     // 0..28

    for (int k0 = 0; k0 < K; k0 += 32) {
#pragma unroll
        for (int t = 0; t < 4; t++) {
            int r = lr + t * 32;
            float4 v = *(const float4*)(A + (size_t)(row0 + r) * K + k0 + lc);
            As[r][lc]     = f2tf(v.x);
            As[r][lc + 1] = f2tf(v.y);
            As[r][lc + 2] = f2tf(v.z);
            As[r][lc + 3] = f2tf(v.w);
        }
#pragma unroll
        for (int t = 0; t < 4; t++) {
            int r = lr + t * 32;
            int g = col0 + r;
            float4 v = make_float4(0.f, 0.f, 0.f, 0.f);
            if (g < N) v = *(const float4*)(W + (size_t)g * K + k0 + lc);
            Bs[r][lc]     = f2tf(v.x);
            Bs[r][lc + 1] = f2tf(v.y);
            Bs[r][lc + 2] = f2tf(v.z);
            Bs[r][lc + 3] = f2tf(v.w);
        }
        __syncthreads();

#pragma unroll
        for (int ks = 0; ks < 4; ks++) {
            int kk = ks * 8 + (lane & 3);
            int mrow = wm + (lane >> 2);
            int nrow = wn + (lane >> 2);
            unsigned af[4][4], bf[4][2];
#pragma unroll
            for (int i = 0; i < 4; i++) {
                af[i][0] = As[mrow + i * 16][kk];
                af[i][1] = As[mrow + i * 16 + 8][kk];
                af[i][2] = As[mrow + i * 16][kk + 4];
                af[i][3] = As[mrow + i * 16 + 8][kk + 4];
            }
#pragma unroll
            for (int j = 0; j < 4; j++) {
                bf[j][0] = Bs[nrow + j * 8][kk];
                bf[j][1] = Bs[nrow + j * 8][kk + 4];
            }
#pragma unroll
            for (int i = 0; i < 4; i++)
#pragma unroll
                for (int j = 0; j < 4; j++)
                    mma_tf32(acc[i][j], af[i], bf[j]);
        }
        __syncthreads();
    }

    // Epilogue: c0,c1 at (row, col..col+1); c2,c3 at (row+8, ...)
    int rbase = row0 + wm + (lane >> 2);
    int cbase = col0 + wn + 2 * (lane & 3);
#pragma unroll
    for (int i = 0; i < 4; i++) {
#pragma unroll
        for (int j = 0; j < 4; j++) {
            int r = rbase + i * 16;
            int c = cbase + j * 8;
            if (c < N) {
                *(float2*)(C + (size_t)r * N + c) =
                    make_float2(acc[i][j][0], acc[i][j][1]);
                *(float2*)(C + (size_t)(r + 8) * N + c) =
                    make_float2(acc[i][j][2], acc[i][j][3]);
            }
        }
    }
}

// ---------------------------------------------------------------------------
// RoPE
// ---------------------------------------------------------------------------
__global__ void rope_q_kernel(float* __restrict__ q) {
    int idx = blockIdx.x * blockDim.x + threadIdx.x;
    if (idx >= MM * HH * 32) return;
    int i  = idx & 31;
    int h  = (idx >> 5) & (HH - 1);
    int ms = idx >> 9;
    int s  = ms & (SS - 1);
    float f = exp2f(-(float)i * (1.f / 32.f) * log2f(10000.f));
    float ang = (float)s * f;
    float sn, c;
    sincosf(ang, &sn, &c);
    float* base = q + (size_t)ms * DD + h * HD_ + ND_ + 2 * i;
    float x0 = base[0], x1 = base[1];
    base[0] = x0 * c - x1 * sn;
    base[1] = x1 * c + x0 * sn;
}

__global__ void rope_k_kernel(float* __restrict__ kr) {
    int idx = blockIdx.x * blockDim.x + threadIdx.x;
    if (idx >= MM * 32) return;
    int i  = idx & 31;
    int ms = idx >> 5;
    int s  = ms & (SS - 1);
    float f = exp2f(-(float)i * (1.f / 32.f) * log2f(10000.f));
    float ang = (float)s * f;
    float sn, c;
    sincosf(ang, &sn, &c);
    float* base = kr + (size_t)ms * RD_ + 2 * i;
    float x0 = base[0], x1 = base[1];
    base[0] = x0 * c - x1 * sn;
    base[1] = x1 * c + x0 * sn;
}

// ---------------------------------------------------------------------------
// Flash attention (fp32, unchanged this round)
// ---------------------------------------------------------------------------
#define ATTN_SMEM ((64*128 + 128*64 + 64*128 + 64*64) * 4)

__global__ void __launch_bounds__(256) mla_attn_kernel(
        const float* __restrict__ q,  const float* __restrict__ knope,
        const float* __restrict__ kr, const float* __restrict__ v,
        float* __restrict__ out) {
    extern __shared__ float sm[];
    float* Qs  = sm;
    float* KsT = Qs  + 64 * 128;
    float* Vs  = KsT + 128 * 64;
    float* Ps  = Vs  + 64 * 128;

    int qb = blockIdx.x, h = blockIdx.y, b = blockIdx.z;
    int tid = threadIdx.x;
    int tx = tid & 15, ty = tid >> 4;
    int q0 = qb * 64;
    size_t bs = (size_t)b * SS;

#pragma unroll
    for (int t = 0; t < 8; t++) {
        int idx = tid + t * 256;
        int r = idx >> 5;
        int c = (idx & 31) << 2;
        *(float4*)&Qs[r * 128 + c] =
            *(const float4*)(q + (bs + q0 + r) * DD + h * HD_ + c);
    }

    float m_[4], l_[4], O[4][8];
#pragma unroll
    for (int i = 0; i < 4; i++) {
        m_[i] = -1e30f; l_[i] = 0.f;
#pragma unroll
        for (int d = 0; d < 8; d++) O[i][d] = 0.f;
    }
    const float scale = 0.08838834764831845f;
    __syncthreads();

    for (int kb = 0; kb <= qb; kb++) {
        int k0 = kb * 64;
#pragma unroll
        for (int t = 0; t < 4; t++) {
            int idx = tid + t * 256;
            int r = idx >> 4;
            int c = (idx & 15) << 2;
            float4 kn = *(const float4*)(knope + (bs + k0 + r) * (HH * ND_) + h * ND_ + c);
            KsT[(c    ) * 64 + r] = kn.x;
            KsT[(c + 1) * 64 + r] = kn.y;
            KsT[(c + 2) * 64 + r] = kn.z;
            KsT[(c + 3) * 64 + r] = kn.w;
            float4 kp = *(const float4*)(kr + (bs + k0 + r) * RD_ + c);
            KsT[(64 + c    ) * 64 + r] = kp.x;
            KsT[(64 + c + 1) * 64 + r] = kp.y;
            KsT[(64 + c + 2) * 64 + r] = kp.z;
            KsT[(64 + c + 3) * 64 + r] = kp.w;
        }
#pragma unroll
        for (int t = 0; t < 8; t++) {
            int idx = tid + t * 256;
            int r = idx >> 5;
            int c = (idx & 31) << 2;
            *(float4*)&Vs[r * 128 + c] =
                *(const float4*)(v + (bs + k0 + r) * DD + h * HD_ + c);
        }
        __syncthreads();

        float sacc[4][4];
#pragma unroll
        for (int i = 0; i < 4; i++)
#pragma unroll
            for (int j = 0; j < 4; j++) sacc[i][j] = 0.f;

#pragma unroll 8
        for (int kk = 0; kk < 128; kk++) {
            float4 kv = *(float4*)&KsT[kk * 64 + tx * 4];
            float kvr[4] = {kv.x, kv.y, kv.z, kv.w};
#pragma unroll
            for (int i = 0; i < 4; i++) {
                float qv = Qs[(ty * 4 + i) * 128 + kk];
#pragma unroll
                for (int j = 0; j < 4; j++)
                    sacc[i][j] += qv * kvr[j];
            }
        }

#pragma unroll
        for (int i = 0; i < 4; i++) {
            int qi = q0 + ty * 4 + i;
#pragma unroll
            for (int j = 0; j < 4; j++) {
                int ki = k0 + tx * 4 + j;
                sacc[i][j] = (ki <= qi) ? sacc[i][j] * scale : -1e30f;
            }
            float mloc = fmaxf(fmaxf(sacc[i][0], sacc[i][1]),
                               fmaxf(sacc[i][2], sacc[i][3]));
#pragma unroll
            for (int off = 8; off >= 1; off >>= 1)
                mloc = fmaxf(mloc, __shfl_xor_sync(0xffffffffu, mloc, off, 16));
            float mnew = fmaxf(m_[i], mloc);
            float corr = __expf(m_[i] - mnew);
            float rs = 0.f;
#pragma unroll
            for (int j = 0; j < 4; j++) {
                float p = __expf(sacc[i][j] - mnew);
                Ps[(ty * 4 + i) * 64 + tx * 4 + j] = p;
                rs += p;
            }
#pragma unroll
            for (int off = 8; off >= 1; off >>= 1)
                rs += __shfl_xor_sync(0xffffffffu, rs, off, 16);
            l_[i] = l_[i] * corr + rs;
            m_[i] = mnew;
#pragma unroll
            for (int d = 0; d < 8; d++) O[i][d] *= corr;
        }
        __syncthreads();

#pragma unroll 4
        for (int k = 0; k < 64; k++) {
            float4 v0 = *(float4*)&Vs[k * 128 + tx * 8];
            float4 v1 = *(float4*)&Vs[k * 128 + tx * 8 + 4];
            float vv[8] = {v0.x, v0.y, v0.z, v0.w, v1.x, v1.y, v1.z, v1.w};
#pragma unroll
            for (int i = 0; i < 4; i++) {
                float p = Ps[(ty * 4 + i) * 64 + k];
#pragma unroll
                for (int d = 0; d < 8; d++)
                    O[i][d] += p * vv[d];
            }
        }
        __syncthreads();
    }

#pragma unroll
    for (int i = 0; i < 4; i++) {
        float inv = 1.f / l_[i];
        size_t rowp = (bs + q0 + ty * 4 + i) * DD + h * HD_ + tx * 8;
#pragma unroll
        for (int d = 0; d < 8; d++)
            out[rowp + d] = O[i][d] * inv;
    }
}

// ---------------------------------------------------------------------------
extern "C" void kernel_launch(void* const* d_in, const int* in_sizes, int n_in,
                              void* d_out, int out_size) {
    const float* x   = (const float*)d_in[0];
    const float* wq  = (const float*)d_in[1];
    const float* wkd = (const float*)d_in[2];
    const float* wku = (const float*)d_in[3];
    const float* wkr = (const float*)d_in[4];
    const float* wvu = (const float*)d_in[5];
    const float* wo  = (const float*)d_in[6];
    float* out = (float*)d_out;

    float *pq, *pckv, *pkn, *pkr, *pv, *pattn;
    cudaGetSymbolAddress((void**)&pq,    g_q);
    cudaGetSymbolAddress((void**)&pckv,  g_ckv);
    cudaGetSymbolAddress((void**)&pkn,   g_kn);
    cudaGetSymbolAddress((void**)&pkr,   g_kr);
    cudaGetSymbolAddress((void**)&pv,    g_v);
    cudaGetSymbolAddress((void**)&pattn, g_attn);

    cudaFuncSetAttribute(mla_attn_kernel,
                         cudaFuncAttributeMaxDynamicSharedMemorySize, ATTN_SMEM);

    gemm_tf32<<<dim3(DD / 128, MM / 128), 256>>>(x, wq, pq, MM, DD, DD);
    gemm_tf32<<<dim3(RR / 128, MM / 128), 256>>>(x, wkd, pckv, MM, RR, DD);
    gemm_tf32<<<dim3(1, MM / 128), 256>>>(x, wkr, pkr, MM, RD_, DD);
    gemm_tf32<<<dim3((HH * ND_) / 128, MM / 128), 256>>>(pckv, wku, pkn, MM, HH * ND_, RR);
    gemm_tf32<<<dim3(DD / 128, MM / 128), 256>>>(pckv, wvu, pv, MM, DD, RR);
    rope_q_kernel<<<(MM * HH * 32) / 256, 256>>>(pq);
    rope_k_kernel<<<(MM * 32) / 256, 256>>>(pkr);
    mla_attn_kernel<<<dim3(SS / 64, HH, BB), 256, ATTN_SMEM>>>(pq, pkn, pkr, pv, pattn);
    gemm_tf32<<<dim3(DD / 128, MM / 128), 256>>>(pattn, wo, out, MM, DD, DD);
}

// round 3
// speedup vs baseline: 3.3982x; 1.8812x over previous
#include <cuda_runtime.h>
#include <math.h>

// Problem constants
#define BB 2
#define SS 2048
#define DD 2048
#define HH 16
#define HD_ 128
#define ND_ 64
#define RD_ 64
#define RR 512
#define MM (BB*SS)   // 4096

// Scratch (device globals: no allocation allowed)
__device__ float g_q   [(size_t)MM*DD];
__device__ float g_ckv [(size_t)MM*RR];
__device__ float g_kn  [(size_t)MM*HH*ND_];
__device__ float g_kr  [(size_t)MM*RD_];
__device__ float g_v   [(size_t)MM*DD];
__device__ float g_attn[(size_t)MM*DD];

__device__ __forceinline__ unsigned f2tf(float x) {
    unsigned y;
    asm("cvt.rna.tf32.f32 %0, %1;" : "=r"(y) : "f"(x));
    return y;
}

__device__ __forceinline__ void mma_tf32(float d[4], const unsigned a[4],
                                         const unsigned b[2]) {
    asm volatile(
        "mma.sync.aligned.m16n8k8.row.col.f32.tf32.tf32.f32 "
        "{%0,%1,%2,%3}, {%4,%5,%6,%7}, {%8,%9}, {%0,%1,%2,%3};\n"
        : "+f"(d[0]), "+f"(d[1]), "+f"(d[2]), "+f"(d[3])
        : "r"(a[0]), "r"(a[1]), "r"(a[2]), "r"(a[3]),
          "r"(b[0]), "r"(b[1]));
}

// ---------------------------------------------------------------------------
// C[M,N] = A[M,K] @ W[N,K]^T  via tf32 tensor cores.
// Block 128x128, BK=32, 256 threads = 8 warps (2m x 4n), warp tile 64x32.
// ---------------------------------------------------------------------------
__global__ void __launch_bounds__(256) gemm_tf32(const float* __restrict__ A,
                                                 const float* __restrict__ W,
                                                 float* __restrict__ C,
                                                 int M, int N, int K) {
    __shared__ unsigned As[128][36];
    __shared__ unsigned Bs[128][36];
    int tid = threadIdx.x;
    int lane = tid & 31, warp = tid >> 5;
    int wm = (warp & 1) * 64;
    int wn = (warp >> 1) * 32;
    int row0 = blockIdx.y * 128, col0 = blockIdx.x * 128;

    float acc[4][4][4];
#pragma unroll
    for (int i = 0; i < 4; i++)
#pragma unroll
        for (int j = 0; j < 4; j++)
#pragma unroll
            for (int r = 0; r < 4; r++) acc[i][j][r] = 0.f;

    int lr = tid >> 3;
    int lc = (tid & 7) * 4;

    for (int k0 = 0; k0 < K; k0 += 32) {
#pragma unroll
        for (int t = 0; t < 4; t++) {
            int r = lr + t * 32;
            float4 v = *(const float4*)(A + (size_t)(row0 + r) * K + k0 + lc);
            As[r][lc]     = f2tf(v.x);
            As[r][lc + 1] = f2tf(v.y);
            As[r][lc + 2] = f2tf(v.z);
            As[r][lc + 3] = f2tf(v.w);
        }
#pragma unroll
        for (int t = 0; t < 4; t++) {
            int r = lr + t * 32;
            int g = col0 + r;
            float4 v = make_float4(0.f, 0.f, 0.f, 0.f);
            if (g < N) v = *(const float4*)(W + (size_t)g * K + k0 + lc);
            Bs[r][lc]     = f2tf(v.x);
            Bs[r][lc + 1] = f2tf(v.y);
            Bs[r][lc + 2] = f2tf(v.z);
            Bs[r][lc + 3] = f2tf(v.w);
        }
        __syncthreads();

#pragma unroll
        for (int ks = 0; ks < 4; ks++) {
            int kk = ks * 8 + (lane & 3);
            int mrow = wm + (lane >> 2);
            int nrow = wn + (lane >> 2);
            unsigned af[4][4], bf[4][2];
#pragma unroll
            for (int i = 0; i < 4; i++) {
                af[i][0] = As[mrow + i * 16][kk];
                af[i][1] = As[mrow + i * 16 + 8][kk];
                af[i][2] = As[mrow + i * 16][kk + 4];
                af[i][3] = As[mrow + i * 16 + 8][kk + 4];
            }
#pragma unroll
            for (int j = 0; j < 4; j++) {
                bf[j][0] = Bs[nrow + j * 8][kk];
                bf[j][1] = Bs[nrow + j * 8][kk + 4];
            }
#pragma unroll
            for (int i = 0; i < 4; i++)
#pragma unroll
                for (int j = 0; j < 4; j++)
                    mma_tf32(acc[i][j], af[i], bf[j]);
        }
        __syncthreads();
    }

    int rbase = row0 + wm + (lane >> 2);
    int cbase = col0 + wn + 2 * (lane & 3);
#pragma unroll
    for (int i = 0; i < 4; i++) {
#pragma unroll
        for (int j = 0; j < 4; j++) {
            int r = rbase + i * 16;
            int c = cbase + j * 8;
            if (c < N) {
                *(float2*)(C + (size_t)r * N + c) =
                    make_float2(acc[i][j][0], acc[i][j][1]);
                *(float2*)(C + (size_t)(r + 8) * N + c) =
                    make_float2(acc[i][j][2], acc[i][j][3]);
            }
        }
    }
}

// ---------------------------------------------------------------------------
// RoPE
// ---------------------------------------------------------------------------
__global__ void rope_q_kernel(float* __restrict__ q) {
    int idx = blockIdx.x * blockDim.x + threadIdx.x;
    if (idx >= MM * HH * 32) return;
    int i  = idx & 31;
    int h  = (idx >> 5) & (HH - 1);
    int ms = idx >> 9;
    int s  = ms & (SS - 1);
    float f = exp2f(-(float)i * (1.f / 32.f) * log2f(10000.f));
    float ang = (float)s * f;
    float sn, c;
    sincosf(ang, &sn, &c);
    float* base = q + (size_t)ms * DD + h * HD_ + ND_ + 2 * i;
    float x0 = base[0], x1 = base[1];
    base[0] = x0 * c - x1 * sn;
    base[1] = x1 * c + x0 * sn;
}

__global__ void rope_k_kernel(float* __restrict__ kr) {
    int idx = blockIdx.x * blockDim.x + threadIdx.x;
    if (idx >= MM * 32) return;
    int i  = idx & 31;
    int ms = idx >> 5;
    int s  = ms & (SS - 1);
    float f = exp2f(-(float)i * (1.f / 32.f) * log2f(10000.f));
    float ang = (float)s * f;
    float sn, c;
    sincosf(ang, &sn, &c);
    float* base = kr + (size_t)ms * RD_ + 2 * i;
    float x0 = base[0], x1 = base[1];
    base[0] = x0 * c - x1 * sn;
    base[1] = x1 * c + x0 * sn;
}

// ---------------------------------------------------------------------------
// Flash attention with tf32 tensor cores.
// Q tile 128 x K tile 64, 8 warps; warp w owns rows w*16..w*16+15 (full width)
// so softmax is warp-local. P round-trips through smem (layout conversion).
// Strides padded for conflict-free fragment LDS.
// ---------------------------------------------------------------------------
#define AQ 128
#define AKT 64
#define QSTR 132
#define KSTR 132
#define VSTR 136
#define PSTR 68
#define ATTN_SMEM ((AQ*QSTR + AKT*KSTR + AKT*VSTR + AQ*PSTR) * 4)

__global__ void __launch_bounds__(256) mla_attn_mma(
        const float* __restrict__ q,  const float* __restrict__ knope,
        const float* __restrict__ kr, const float* __restrict__ v,
        float* __restrict__ out) {
    extern __shared__ unsigned sm[];
    unsigned* Qs = sm;                   // [128][132]
    unsigned* Ks = Qs + AQ * QSTR;       // [64][132]
    unsigned* Vs = Ks + AKT * KSTR;      // [64][136]
    unsigned* Ps = Vs + AKT * VSTR;      // [128][68]

    int qb = blockIdx.x, h = blockIdx.y, b = blockIdx.z;
    int tid = threadIdx.x, lane = tid & 31, warp = tid >> 5;
    int q0 = qb * AQ;
    size_t bs = (size_t)b * SS;
    int wr = warp * 16;
    int gr = lane >> 2, gt = lane & 3;
    const float scale = 0.08838834764831845f;

    // Load+convert Q tile: 128 rows x 32 float4
#pragma unroll
    for (int t = 0; t < 16; t++) {
        int idx = tid + t * 256;
        int r = idx >> 5, c = (idx & 31) << 2;
        float4 vq = *(const float4*)(q + (bs + q0 + r) * DD + h * HD_ + c);
        unsigned* p = &Qs[r * QSTR + c];
        p[0] = f2tf(vq.x); p[1] = f2tf(vq.y);
        p[2] = f2tf(vq.z); p[3] = f2tf(vq.w);
    }

    float m0 = -1e30f, m1 = -1e30f, l0 = 0.f, l1 = 0.f;
    float Of[16][4];
#pragma unroll
    for (int j = 0; j < 16; j++)
#pragma unroll
        for (int r = 0; r < 4; r++) Of[j][r] = 0.f;
    __syncthreads();

    int kbmax = 2 * qb + 1;
    for (int kb = 0; kb <= kbmax; kb++) {
        int k0 = kb * AKT;
        // Load K (nope|rope) and V: 64 rows x 32 float4 each
#pragma unroll
        for (int t = 0; t < 8; t++) {
            int idx = tid + t * 256;
            int r = idx >> 5, c = (idx & 31) << 2;
            float4 kv;
            if (c < 64)
                kv = *(const float4*)(knope + (bs + k0 + r) * (HH * ND_) + h * ND_ + c);
            else
                kv = *(const float4*)(kr + (bs + k0 + r) * RD_ + (c - 64));
            unsigned* pk = &Ks[r * KSTR + c];
            pk[0] = f2tf(kv.x); pk[1] = f2tf(kv.y);
            pk[2] = f2tf(kv.z); pk[3] = f2tf(kv.w);
            float4 vv = *(const float4*)(v + (bs + k0 + r) * DD + h * HD_ + c);
            unsigned* pv = &Vs[r * VSTR + c];
            pv[0] = f2tf(vv.x); pv[1] = f2tf(vv.y);
            pv[2] = f2tf(vv.z); pv[3] = f2tf(vv.w);
        }
        __syncthreads();

        // S = Q @ K^T : per warp m16 x n64, k=128
        float sacc[8][4];
#pragma unroll
        for (int j = 0; j < 8; j++)
#pragma unroll
            for (int r = 0; r < 4; r++) sacc[j][r] = 0.f;

#pragma unroll
        for (int ks = 0; ks < 16; ks++) {
            int kk = ks * 8 + gt;
            unsigned a[4];
            a[0] = Qs[(wr + gr) * QSTR + kk];
            a[1] = Qs[(wr + gr + 8) * QSTR + kk];
            a[2] = Qs[(wr + gr) * QSTR + kk + 4];
            a[3] = Qs[(wr + gr + 8) * QSTR + kk + 4];
#pragma unroll
            for (int j = 0; j < 8; j++) {
                unsigned bf[2];
                bf[0] = Ks[(j * 8 + gr) * KSTR + kk];
                bf[1] = Ks[(j * 8 + gr) * KSTR + kk + 4];
                mma_tf32(sacc[j], a, bf);
            }
        }

        // Online softmax (warp-local; rows r0g and r1g per thread)
        int r0g = q0 + wr + gr, r1g = r0g + 8;
        float mn0 = m0, mn1 = m1;
#pragma unroll
        for (int j = 0; j < 8; j++) {
            int c = k0 + j * 8 + 2 * gt;
            sacc[j][0] = (c     <= r0g) ? sacc[j][0] * scale : -1e30f;
            sacc[j][1] = (c + 1 <= r0g) ? sacc[j][1] * scale : -1e30f;
            sacc[j][2] = (c     <= r1g) ? sacc[j][2] * scale : -1e30f;
            sacc[j][3] = (c + 1 <= r1g) ? sacc[j][3] * scale : -1e30f;
            mn0 = fmaxf(mn0, fmaxf(sacc[j][0], sacc[j][1]));
            mn1 = fmaxf(mn1, fmaxf(sacc[j][2], sacc[j][3]));
        }
        mn0 = fmaxf(mn0, __shfl_xor_sync(0xffffffffu, mn0, 1));
        mn0 = fmaxf(mn0, __shfl_xor_sync(0xffffffffu, mn0, 2));
        mn1 = fmaxf(mn1, __shfl_xor_sync(0xffffffffu, mn1, 1));
        mn1 = fmaxf(mn1, __shfl_xor_sync(0xffffffffu, mn1, 2));
        float corr0 = __expf(m0 - mn0), corr1 = __expf(m1 - mn1);
        m0 = mn0; m1 = mn1;
        float rs0 = 0.f, rs1 = 0.f;
#pragma unroll
        for (int j = 0; j < 8; j++) {
            float p00 = __expf(sacc[j][0] - m0);
            float p01 = __expf(sacc[j][1] - m0);
            float p10 = __expf(sacc[j][2] - m1);
            float p11 = __expf(sacc[j][3] - m1);
            rs0 += p00 + p01; rs1 += p10 + p11;
            unsigned* pp0 = &Ps[(wr + gr) * PSTR + j * 8 + 2 * gt];
            pp0[0] = f2tf(p00); pp0[1] = f2tf(p01);
            unsigned* pp1 = &Ps[(wr + gr + 8) * PSTR + j * 8 + 2 * gt];
            pp1[0] = f2tf(p10); pp1[1] = f2tf(p11);
        }
        rs0 += __shfl_xor_sync(0xffffffffu, rs0, 1);
        rs0 += __shfl_xor_sync(0xffffffffu, rs0, 2);
        rs1 += __shfl_xor_sync(0xffffffffu, rs1, 1);
        rs1 += __shfl_xor_sync(0xffffffffu, rs1, 2);
        l0 = l0 * corr0 + rs0;
        l1 = l1 * corr1 + rs1;
#pragma unroll
        for (int j = 0; j < 16; j++) {
            Of[j][0] *= corr0; Of[j][1] *= corr0;
            Of[j][2] *= corr1; Of[j][3] *= corr1;
        }
        __syncwarp();

        // O += P @ V : per warp m16 x n128, k=64 (P rows are warp-private)
#pragma unroll
        for (int ks = 0; ks < 8; ks++) {
            int kk = ks * 8 + gt;
            unsigned a[4];
            a[0] = Ps[(wr + gr) * PSTR + kk];
            a[1] = Ps[(wr + gr + 8) * PSTR + kk];
            a[2] = Ps[(wr + gr) * PSTR + kk + 4];
            a[3] = Ps[(wr + gr + 8) * PSTR + kk + 4];
#pragma unroll
            for (int j = 0; j < 16; j++) {
                unsigned bf[2];
                bf[0] = Vs[kk * VSTR + j * 8 + gr];
                bf[1] = Vs[(kk + 4) * VSTR + j * 8 + gr];
                mma_tf32(Of[j], a, bf);
            }
        }
        __syncthreads();
    }

    float inv0 = 1.f / l0, inv1 = 1.f / l1;
    size_t row0p = (bs + q0 + wr + gr) * DD + h * HD_;
    size_t row1p = row0p + (size_t)8 * DD;
#pragma unroll
    for (int j = 0; j < 16; j++) {
        int c = j * 8 + 2 * gt;
        *(float2*)(out + row0p + c) = make_float2(Of[j][0] * inv0, Of[j][1] * inv0);
        *(float2*)(out + row1p + c) = make_float2(Of[j][2] * inv1, Of[j][3] * inv1);
    }
}

// ---------------------------------------------------------------------------
extern "C" void kernel_launch(void* const* d_in, const int* in_sizes, int n_in,
                              void* d_out, int out_size) {
    const float* x   = (const float*)d_in[0];
    const float* wq  = (const float*)d_in[1];
    const float* wkd = (const float*)d_in[2];
    const float* wku = (const float*)d_in[3];
    const float* wkr = (const float*)d_in[4];
    const float* wvu = (const float*)d_in[5];
    const float* wo  = (const float*)d_in[6];
    float* out = (float*)d_out;

    float *pq, *pckv, *pkn, *pkr, *pv, *pattn;
    cudaGetSymbolAddress((void**)&pq,    g_q);
    cudaGetSymbolAddress((void**)&pckv,  g_ckv);
    cudaGetSymbolAddress((void**)&pkn,   g_kn);
    cudaGetSymbolAddress((void**)&pkr,   g_kr);
    cudaGetSymbolAddress((void**)&pv,    g_v);
    cudaGetSymbolAddress((void**)&pattn, g_attn);

    cudaFuncSetAttribute(mla_attn_mma,
                         cudaFuncAttributeMaxDynamicSharedMemorySize, ATTN_SMEM);

    gemm_tf32<<<dim3(DD / 128, MM / 128), 256>>>(x, wq, pq, MM, DD, DD);
    gemm_tf32<<<dim3(RR / 128, MM / 128), 256>>>(x, wkd, pckv, MM, RR, DD);
    gemm_tf32<<<dim3(1, MM / 128), 256>>>(x, wkr, pkr, MM, RD_, DD);
    gemm_tf32<<<dim3((HH * ND_) / 128, MM / 128), 256>>>(pckv, wku, pkn, MM, HH * ND_, RR);
    gemm_tf32<<<dim3(DD / 128, MM / 128), 256>>>(pckv, wvu, pv, MM, DD, RR);
    rope_q_kernel<<<(MM * HH * 32) / 256, 256>>>(pq);
    rope_k_kernel<<<(MM * 32) / 256, 256>>>(pkr);
    mla_attn_mma<<<dim3(SS / AQ, HH, BB), 256, ATTN_SMEM>>>(pq, pkn, pkr, pv, pattn);
    gemm_tf32<<<dim3(DD / 128, MM / 128), 256>>>(pattn, wo, out, MM, DD, DD);
}

// round 5
// speedup vs baseline: 3.6109x; 1.0626x over previous
#include <cuda_runtime.h>
#include <math.h>
#include <stdint.h>

// Problem constants
#define BB 2
#define SS 2048
#define DD 2048
#define HH 16
#define HD_ 128
#define ND_ 64
#define RD_ 64
#define RR 512
#define MM (BB*SS)   // 4096

// Scratch (device globals: no allocation allowed)
__device__ float g_q   [(size_t)MM*DD];
__device__ float g_ckv [(size_t)MM*RR];
__device__ float g_kn  [(size_t)MM*HH*ND_];
__device__ float g_kr  [(size_t)MM*RD_];
__device__ float g_v   [(size_t)MM*DD];
__device__ float g_attn[(size_t)MM*DD];

// ---------------------------------------------------------------------------
// Helpers (baseline-ISA only: mma.sync + ldmatrix; NO tcgen05)
// ---------------------------------------------------------------------------
__device__ __forceinline__ uint32_t smem_u32(const void* p) {
    uint32_t a;
    asm("{ .reg .u64 t; cvta.to.shared.u64 t, %1; cvt.u32.u64 %0, t; }"
        : "=r"(a) : "l"(p));
    return a;
}
__device__ __forceinline__ unsigned f2tf(float x) {
    unsigned y;
    asm("cvt.rna.tf32.f32 %0, %1;" : "=r"(y) : "f"(x));
    return y;
}
__device__ __forceinline__ void mma_tf32(float d[4], const unsigned a[4],
                                         const unsigned b[2]) {
    asm volatile(
        "mma.sync.aligned.m16n8k8.row.col.f32.tf32.tf32.f32 "
        "{%0,%1,%2,%3}, {%4,%5,%6,%7}, {%8,%9}, {%0,%1,%2,%3};\n"
        : "+f"(d[0]), "+f"(d[1]), "+f"(d[2]), "+f"(d[3])
        : "r"(a[0]), "r"(a[1]), "r"(a[2]), "r"(a[3]),
          "r"(b[0]), "r"(b[1]));
}
__device__ __forceinline__ void ldsm_x4(unsigned r[4], uint32_t addr) {
    asm volatile("ldmatrix.sync.aligned.m8n8.x4.shared.b16 {%0,%1,%2,%3}, [%4];"
                 : "=r"(r[0]), "=r"(r[1]), "=r"(r[2]), "=r"(r[3]) : "r"(addr));
}

// ---------------------------------------------------------------------------
// tf32 GEMM: C[M,N] = A[M,K] @ W[N,K]^T
// Block 128x128, BK=32, 256 thr = 8 warps (2m x 4n), warp tile 64x32.
// ldmatrix fragment feeds + 2-stage double buffer with register prefetch.
// ---------------------------------------------------------------------------
#define GSTR 36
#define G_TILE (128*GSTR)
#define G_SMEM (4*G_TILE*4)   // 73728 B

__global__ void __launch_bounds__(256) gemm_tf32(const float* __restrict__ A,
                                                 const float* __restrict__ W,
                                                 float* __restrict__ C,
                                                 int M, int N, int K) {
    extern __shared__ unsigned smg[];
    int tid = threadIdx.x, lane = tid & 31, warp = tid >> 5;
    int wm = (warp & 1) * 64, wn = (warp >> 1) * 32;
    int row0 = blockIdx.y * 128, col0 = blockIdx.x * 128;

    float acc[4][4][4];
#pragma unroll
    for (int i = 0; i < 4; i++)
#pragma unroll
        for (int j = 0; j < 4; j++)
#pragma unroll
            for (int r = 0; r < 4; r++) acc[i][j][r] = 0.f;

    int lr = tid >> 3;          // 0..31
    int lc = (tid & 7) * 4;     // 0..28

    // ldmatrix lane address components
    int laneRowA = (lane & 7) + ((lane >> 3) & 1) * 8;   // + wm + i*16
    int laneColA = ((lane >> 4) & 1) * 4;                // + ks*8
    int laneRowB = (lane & 7) + ((lane >> 4) & 1) * 8;   // + wn + jp*16
    int laneColB = ((lane >> 3) & 1) * 4;                // + ks*8

    float4 pa[4], pb[4];
#pragma unroll
    for (int t = 0; t < 4; t++) {
        pa[t] = *(const float4*)(A + (size_t)(row0 + lr + t * 32) * K + lc);
        int g = col0 + lr + t * 32;
        pb[t] = make_float4(0.f, 0.f, 0.f, 0.f);
        if (g < N) pb[t] = *(const float4*)(W + (size_t)g * K + lc);
    }

    int NS = K >> 5;
    for (int s = 0; s < NS; s++) {
        unsigned* Ab = smg + (s & 1) * 2 * G_TILE;
        unsigned* Bb = Ab + G_TILE;
#pragma unroll
        for (int t = 0; t < 4; t++) {
            unsigned* p = &Ab[(lr + t * 32) * GSTR + lc];
            p[0] = f2tf(pa[t].x); p[1] = f2tf(pa[t].y);
            p[2] = f2tf(pa[t].z); p[3] = f2tf(pa[t].w);
            unsigned* q = &Bb[(lr + t * 32) * GSTR + lc];
            q[0] = f2tf(pb[t].x); q[1] = f2tf(pb[t].y);
            q[2] = f2tf(pb[t].z); q[3] = f2tf(pb[t].w);
        }
        __syncthreads();
        if (s + 1 < NS) {
            int k0 = (s + 1) << 5;
#pragma unroll
            for (int t = 0; t < 4; t++) {
                pa[t] = *(const float4*)(A + (size_t)(row0 + lr + t * 32) * K + k0 + lc);
                int g = col0 + lr + t * 32;
                if (g < N)
                    pb[t] = *(const float4*)(W + (size_t)g * K + k0 + lc);
            }
        }
        uint32_t AbU = smem_u32(Ab), BbU = smem_u32(Bb);
#pragma unroll
        for (int ks = 0; ks < 4; ks++) {
            unsigned bfr[2][4];
#pragma unroll
            for (int jp = 0; jp < 2; jp++)
                ldsm_x4(bfr[jp], BbU + (uint32_t)(((wn + jp * 16 + laneRowB) * GSTR)
                                                  + ks * 8 + laneColB) * 4);
#pragma unroll
            for (int i = 0; i < 4; i++) {
                unsigned af[4];
                ldsm_x4(af, AbU + (uint32_t)(((wm + i * 16 + laneRowA) * GSTR)
                                             + ks * 8 + laneColA) * 4);
#pragma unroll
                for (int jp = 0; jp < 2; jp++) {
                    mma_tf32(acc[i][2 * jp],     af, &bfr[jp][0]);
                    mma_tf32(acc[i][2 * jp + 1], af, &bfr[jp][2]);
                }
            }
        }
        // no trailing sync needed: next iter writes the other buffer, and
        // every warp finishes reads before passing the next barrier.
    }

    int rbase = row0 + wm + (lane >> 2);
    int cbase = col0 + wn + 2 * (lane & 3);
#pragma unroll
    for (int i = 0; i < 4; i++) {
#pragma unroll
        for (int j = 0; j < 4; j++) {
            int r = rbase + i * 16;
            int c = cbase + j * 8;
            if (c < N) {
                *(float2*)(C + (size_t)r * N + c) =
                    make_float2(acc[i][j][0], acc[i][j][1]);
                *(float2*)(C + (size_t)(r + 8) * N + c) =
                    make_float2(acc[i][j][2], acc[i][j][3]);
            }
        }
    }
}

// ---------------------------------------------------------------------------
// RoPE
// ---------------------------------------------------------------------------
__global__ void rope_q_kernel(float* __restrict__ q) {
    int idx = blockIdx.x * blockDim.x + threadIdx.x;
    if (idx >= MM * HH * 32) return;
    int i  = idx & 31;
    int h  = (idx >> 5) & (HH - 1);
    int ms = idx >> 9;
    int s  = ms & (SS - 1);
    float f = exp2f(-(float)i * (1.f / 32.f) * log2f(10000.f));
    float ang = (float)s * f;
    float sn, c;
    sincosf(ang, &sn, &c);
    float* base = q + (size_t)ms * DD + h * HD_ + ND_ + 2 * i;
    float x0 = base[0], x1 = base[1];
    base[0] = x0 * c - x1 * sn;
    base[1] = x1 * c + x0 * sn;
}

__global__ void rope_k_kernel(float* __restrict__ kr) {
    int idx = blockIdx.x * blockDim.x + threadIdx.x;
    if (idx >= MM * 32) return;
    int i  = idx & 31;
    int ms = idx >> 5;
    int s  = ms & (SS - 1);
    float f = exp2f(-(float)i * (1.f / 32.f) * log2f(10000.f));
    float ang = (float)s * f;
    float sn, c;
    sincosf(ang, &sn, &c);
    float* base = kr + (size_t)ms * RD_ + 2 * i;
    float x0 = base[0], x1 = base[1];
    base[0] = x0 * c - x1 * sn;
    base[1] = x1 * c + x0 * sn;
}

// ---------------------------------------------------------------------------
// Flash attention, tf32 mma.sync + ldmatrix fragment feeds.
// Q tile 128 x K tile 64; warp w owns rows w*16..w*16+15 (softmax warp-local).
// V stored transposed (VsT[d][k], stride 68) so P@V B-frags use ldmatrix.
// ---------------------------------------------------------------------------
#define AQ 128
#define AKT 64
#define QSTR 132
#define KSTR 132
#define VTSTR 68
#define PSTR 68
#define ATTN_SMEM ((AQ*QSTR + AKT*KSTR + 128*VTSTR + AQ*PSTR) * 4)

__global__ void __launch_bounds__(256) mla_attn_mma(
        const float* __restrict__ q,  const float* __restrict__ knope,
        const float* __restrict__ kr, const float* __restrict__ v,
        float* __restrict__ out) {
    extern __shared__ unsigned sm[];
    unsigned* Qs = sm;                    // [128][132]
    unsigned* Ks = Qs + AQ * QSTR;        // [64][132]
    unsigned* Vt = Ks + AKT * KSTR;       // [128][68]  (d-major, transposed)
    unsigned* Ps = Vt + 128 * VTSTR;      // [128][68]

    int qb = blockIdx.x, h = blockIdx.y, b = blockIdx.z;
    int tid = threadIdx.x, lane = tid & 31, warp = tid >> 5;
    int q0 = qb * AQ;
    size_t bs = (size_t)b * SS;
    int wr = warp * 16;
    int gr = lane >> 2, gt = lane & 3;
    const float scale = 0.08838834764831845f;

    int laneRowA = (lane & 7) + ((lane >> 3) & 1) * 8;
    int laneColA = ((lane >> 4) & 1) * 4;
    int laneRowB = (lane & 7) + ((lane >> 4) & 1) * 8;
    int laneColB = ((lane >> 3) & 1) * 4;

    uint32_t QsU = smem_u32(Qs), KsU = smem_u32(Ks);
    uint32_t VtU = smem_u32(Vt), PsU = smem_u32(Ps);

    // Load+convert Q tile
#pragma unroll
    for (int t = 0; t < 16; t++) {
        int idx = tid + t * 256;
        int r = idx >> 5, c = (idx & 31) << 2;
        float4 vq = *(const float4*)(q + (bs + q0 + r) * DD + h * HD_ + c);
        unsigned* p = &Qs[r * QSTR + c];
        p[0] = f2tf(vq.x); p[1] = f2tf(vq.y);
        p[2] = f2tf(vq.z); p[3] = f2tf(vq.w);
    }

    float m0 = -1e30f, m1 = -1e30f, l0 = 0.f, l1 = 0.f;
    float Of[16][4];
#pragma unroll
    for (int j = 0; j < 16; j++)
#pragma unroll
        for (int r = 0; r < 4; r++) Of[j][r] = 0.f;
    __syncthreads();

    int kbmax = 2 * qb + 1;
    for (int kb = 0; kb <= kbmax; kb++) {
        int k0 = kb * AKT;
        // K (nope|rope) k-major; V transposed with staggered scatter
#pragma unroll
        for (int t = 0; t < 8; t++) {
            int idx = tid + t * 256;
            int r = idx >> 5, c = (idx & 31) << 2;
            float4 kv;
            if (c < 64)
                kv = *(const float4*)(knope + (bs + k0 + r) * (HH * ND_) + h * ND_ + c);
            else
                kv = *(const float4*)(kr + (bs + k0 + r) * RD_ + (c - 64));
            unsigned* pk = &Ks[r * KSTR + c];
            pk[0] = f2tf(kv.x); pk[1] = f2tf(kv.y);
            pk[2] = f2tf(kv.z); pk[3] = f2tf(kv.w);
            float4 vv = *(const float4*)(v + (bs + k0 + r) * DD + h * HD_ + c);
            unsigned w[4] = {f2tf(vv.x), f2tf(vv.y), f2tf(vv.z), f2tf(vv.w)};
#pragma unroll
            for (int qq0 = 0; qq0 < 4; qq0++) {
                int qq = (qq0 + (lane >> 2)) & 3;
                Vt[(c + qq) * VTSTR + r] = w[qq];
            }
        }
        __syncthreads();

        // S = Q @ K^T : per warp m16 x n64, k=128
        float sacc[8][4];
#pragma unroll
        for (int j = 0; j < 8; j++)
#pragma unroll
            for (int r = 0; r < 4; r++) sacc[j][r] = 0.f;

#pragma unroll
        for (int ks = 0; ks < 16; ks++) {
            unsigned af[4];
            ldsm_x4(af, QsU + (uint32_t)(((wr + laneRowA) * QSTR)
                                         + ks * 8 + laneColA) * 4);
#pragma unroll
            for (int jp = 0; jp < 4; jp++) {
                unsigned bf[4];
                ldsm_x4(bf, KsU + (uint32_t)(((jp * 16 + laneRowB) * KSTR)
                                             + ks * 8 + laneColB) * 4);
                mma_tf32(sacc[2 * jp],     af, &bf[0]);
                mma_tf32(sacc[2 * jp + 1], af, &bf[2]);
            }
        }

        // Online softmax (warp-local)
        int r0g = q0 + wr + gr, r1g = r0g + 8;
        float mn0 = m0, mn1 = m1;
#pragma unroll
        for (int j = 0; j < 8; j++) {
            int c = k0 + j * 8 + 2 * gt;
            sacc[j][0] = (c     <= r0g) ? sacc[j][0] * scale : -1e30f;
            sacc[j][1] = (c + 1 <= r0g) ? sacc[j][1] * scale : -1e30f;
            sacc[j][2] = (c     <= r1g) ? sacc[j][2] * scale : -1e30f;
            sacc[j][3] = (c + 1 <= r1g) ? sacc[j][3] * scale : -1e30f;
            mn0 = fmaxf(mn0, fmaxf(sacc[j][0], sacc[j][1]));
            mn1 = fmaxf(mn1, fmaxf(sacc[j][2], sacc[j][3]));
        }
        mn0 = fmaxf(mn0, __shfl_xor_sync(0xffffffffu, mn0, 1));
        mn0 = fmaxf(mn0, __shfl_xor_sync(0xffffffffu, mn0, 2));
        mn1 = fmaxf(mn1, __shfl_xor_sync(0xffffffffu, mn1, 1));
        mn1 = fmaxf(mn1, __shfl_xor_sync(0xffffffffu, mn1, 2));
        float corr0 = __expf(m0 - mn0), corr1 = __expf(m1 - mn1);
        m0 = mn0; m1 = mn1;
        float rs0 = 0.f, rs1 = 0.f;
#pragma unroll
        for (int j = 0; j < 8; j++) {
            float p00 = __expf(sacc[j][0] - m0);
            float p01 = __expf(sacc[j][1] - m0);
            float p10 = __expf(sacc[j][2] - m1);
            float p11 = __expf(sacc[j][3] - m1);
            rs0 += p00 + p01; rs1 += p10 + p11;
            unsigned* pp0 = &Ps[(wr + gr) * PSTR + j * 8 + 2 * gt];
            pp0[0] = f2tf(p00); pp0[1] = f2tf(p01);
            unsigned* pp1 = &Ps[(wr + gr + 8) * PSTR + j * 8 + 2 * gt];
            pp1[0] = f2tf(p10); pp1[1] = f2tf(p11);
        }
        rs0 += __shfl_xor_sync(0xffffffffu, rs0, 1);
        rs0 += __shfl_xor_sync(0xffffffffu, rs0, 2);
        rs1 += __shfl_xor_sync(0xffffffffu, rs1, 1);
        rs1 += __shfl_xor_sync(0xffffffffu, rs1, 2);
        l0 = l0 * corr0 + rs0;
        l1 = l1 * corr1 + rs1;
#pragma unroll
        for (int j = 0; j < 16; j++) {
            Of[j][0] *= corr0; Of[j][1] *= corr0;
            Of[j][2] *= corr1; Of[j][3] *= corr1;
        }
        __syncwarp();

        // O += P @ V : per warp m16 x n128, k=64 (ldmatrix on P and VsT)
#pragma unroll
        for (int ks = 0; ks < 8; ks++) {
            unsigned af[4];
            ldsm_x4(af, PsU + (uint32_t)(((wr + laneRowA) * PSTR)
                                         + ks * 8 + laneColA) * 4);
#pragma unroll
            for (int jp = 0; jp < 8; jp++) {
                unsigned bf[4];
                ldsm_x4(bf, VtU + (uint32_t)(((jp * 16 + laneRowB) * VTSTR)
                                             + ks * 8 + laneColB) * 4);
                mma_tf32(Of[2 * jp],     af, &bf[0]);
                mma_tf32(Of[2 * jp + 1], af, &bf[2]);
            }
        }
        __syncthreads();
    }

    float inv0 = 1.f / l0, inv1 = 1.f / l1;
    size_t row0p = (bs + q0 + wr + gr) * DD + h * HD_;
    size_t row1p = row0p + (size_t)8 * DD;
#pragma unroll
    for (int j = 0; j < 16; j++) {
        int c = j * 8 + 2 * gt;
        *(float2*)(out + row0p + c) = make_float2(Of[j][0] * inv0, Of[j][1] * inv0);
        *(float2*)(out + row1p + c) = make_float2(Of[j][2] * inv1, Of[j][3] * inv1);
    }
}

// ---------------------------------------------------------------------------
extern "C" void kernel_launch(void* const* d_in, const int* in_sizes, int n_in,
                              void* d_out, int out_size) {
    const float* x   = (const float*)d_in[0];
    const float* wq  = (const float*)d_in[1];
    const float* wkd = (const float*)d_in[2];
    const float* wku = (const float*)d_in[3];
    const float* wkr = (const float*)d_in[4];
    const float* wvu = (const float*)d_in[5];
    const float* wo  = (const float*)d_in[6];
    float* out = (float*)d_out;

    float *pq, *pckv, *pkn, *pkr, *pv, *pattn;
    cudaGetSymbolAddress((void**)&pq,    g_q);
    cudaGetSymbolAddress((void**)&pckv,  g_ckv);
    cudaGetSymbolAddress((void**)&pkn,   g_kn);
    cudaGetSymbolAddress((void**)&pkr,   g_kr);
    cudaGetSymbolAddress((void**)&pv,    g_v);
    cudaGetSymbolAddress((void**)&pattn, g_attn);

    cudaFuncSetAttribute(gemm_tf32,
                         cudaFuncAttributeMaxDynamicSharedMemorySize, G_SMEM);
    cudaFuncSetAttribute(mla_attn_mma,
                         cudaFuncAttributeMaxDynamicSharedMemorySize, ATTN_SMEM);

    gemm_tf32<<<dim3(DD / 128, MM / 128), 256, G_SMEM>>>(x, wq, pq, MM, DD, DD);
    gemm_tf32<<<dim3(RR / 128, MM / 128), 256, G_SMEM>>>(x, wkd, pckv, MM, RR, DD);
    gemm_tf32<<<dim3(1, MM / 128), 256, G_SMEM>>>(x, wkr, pkr, MM, RD_, DD);
    gemm_tf32<<<dim3((HH * ND_) / 128, MM / 128), 256, G_SMEM>>>(pckv, wku, pkn, MM, HH * ND_, RR);
    gemm_tf32<<<dim3(DD / 128, MM / 128), 256, G_SMEM>>>(pckv, wvu, pv, MM, DD, RR);
    rope_q_kernel<<<(MM * HH * 32) / 256, 256>>>(pq);
    rope_k_kernel<<<(MM * 32) / 256, 256>>>(pkr);
    mla_attn_mma<<<dim3(SS / AQ, HH, BB), 256, ATTN_SMEM>>>(pq, pkn, pkr, pv, pattn);
    gemm_tf32<<<dim3(DD / 128, MM / 128), 256, G_SMEM>>>(pattn, wo, out, MM, DD, DD);
}